// round 1
// baseline (speedup 1.0000x reference)
#include <cuda_runtime.h>
#include <cuda_bf16.h>
#include <math.h>

// Problem dims
#define NB 2048
#define NN 64
#define ND 256
#define NDH 128

// smem strides (floats)
#define XS_LD 260   // 64 x 260
#define QK_LD 260   // 64 x 260
#define A_LD  68    // 64 x 68
#define WB_LD 264   // 32 x 264 (transposed weight chunk: [kk][o])

#define XS_OFF 0
#define QK_OFF (64 * XS_LD)
#define AB_OFF (QK_OFF + 64 * QK_LD)
#define WB_OFF (AB_OFF + 64 * A_LD)
#define SMEM_FLOATS (WB_OFF + 32 * WB_LD)
#define SMEM_BYTES (SMEM_FLOATS * 4)

__device__ float g_Ast[2 * 64 * 64];  // softmax(adj0), softmax(adj1)

typedef unsigned long long ull;

#define FMA2(d, a, b) \
    asm("fma.rn.f32x2 %0, %1, %2, %0;" : "+l"(d) : "l"(a), "l"(b))

__device__ __forceinline__ float f4c(const float4& v, int u) {
    switch (u) {
        case 0: return v.x;
        case 1: return v.y;
        case 2: return v.z;
        default: return v.w;
    }
}

// Accumulate OUT[64][256] += A[64 rows][K] * B[K][256]
// A rows owned by thread: r = ty*4+ri, read As[r*lda + acol0 + kk]
// B read Bs[kk*ldb + c], thread cols c = tx*4 + 64*g + {0..3}
__device__ __forceinline__ void gemm_tile(
    ull acc[4][8],
    const float* __restrict__ As, int lda, int acol0,
    const float* __restrict__ Bs, int ldb, int kcnt,
    int tx, int ty)
{
    for (int kk4 = 0; kk4 < kcnt; kk4 += 4) {
        float4 av[4];
#pragma unroll
        for (int ri = 0; ri < 4; ri++)
            av[ri] = *(const float4*)(As + (ty * 4 + ri) * lda + acol0 + kk4);
#pragma unroll
        for (int u = 0; u < 4; u++) {
            const float* brow = Bs + (kk4 + u) * ldb + tx * 4;
            ulonglong2 b0 = *(const ulonglong2*)(brow);
            ulonglong2 b1 = *(const ulonglong2*)(brow + 64);
            ulonglong2 b2 = *(const ulonglong2*)(brow + 128);
            ulonglong2 b3 = *(const ulonglong2*)(brow + 192);
#pragma unroll
            for (int ri = 0; ri < 4; ri++) {
                float a = f4c(av[ri], u);
                ull aa;
                asm("mov.b64 %0, {%1, %2};" : "=l"(aa) : "f"(a), "f"(a));
                FMA2(acc[ri][0], aa, b0.x);
                FMA2(acc[ri][1], aa, b0.y);
                FMA2(acc[ri][2], aa, b1.x);
                FMA2(acc[ri][3], aa, b1.y);
                FMA2(acc[ri][4], aa, b2.x);
                FMA2(acc[ri][5], aa, b2.y);
                FMA2(acc[ri][6], aa, b3.x);
                FMA2(acc[ri][7], aa, b3.y);
            }
        }
    }
}

__device__ __forceinline__ void zero_acc(ull acc[4][8]) {
#pragma unroll
    for (int ri = 0; ri < 4; ri++)
#pragma unroll
        for (int j = 0; j < 8; j++) acc[ri][j] = 0ull;
}

// Store accumulator tile to dst (smem or global), optional bias add.
__device__ __forceinline__ void store_acc(
    ull acc[4][8], float* dst, int ldd,
    const float* __restrict__ bias, int tx, int ty)
{
#pragma unroll
    for (int ri = 0; ri < 4; ri++) {
        int r = ty * 4 + ri;
#pragma unroll
        for (int g = 0; g < 4; g++) {
            int c0 = tx * 4 + 64 * g;
            float x0, x1, x2, x3;
            asm("mov.b64 {%0, %1}, %2;" : "=f"(x0), "=f"(x1) : "l"(acc[ri][2 * g]));
            asm("mov.b64 {%0, %1}, %2;" : "=f"(x2), "=f"(x3) : "l"(acc[ri][2 * g + 1]));
            float4 o = make_float4(x0, x1, x2, x3);
            if (bias) {
                float4 bb = *(const float4*)(bias + c0);
                o.x += bb.x; o.y += bb.y; o.z += bb.z; o.w += bb.w;
            }
            *(float4*)(dst + (size_t)r * ldd + c0) = o;
        }
    }
}

// Stage transposed weight chunk: wbuf_t[kk][o] = W[o][k0+kk], kk in [0,32), o in [0,256)
// o < 128 rows come from w_lo, o >= 128 from w_hi (row o-128).
__device__ __forceinline__ void stage_w(
    float* wbuf_t, const float* __restrict__ w_lo,
    const float* __restrict__ w_hi, int k0, int tid)
{
    int o = (tid >> 3);          // base row group; add i*32
    int j = (tid & 7) * 4;       // column within chunk (4 floats)
#pragma unroll
    for (int i = 0; i < 8; i++) {
        int oo = i * 32 + o;
        const float* src = (oo < 128) ? (w_lo + (size_t)oo * ND)
                                      : (w_hi + (size_t)(oo - 128) * ND);
        float4 v = *(const float4*)(src + k0 + j);
        wbuf_t[(j + 0) * WB_LD + oo] = v.x;
        wbuf_t[(j + 1) * WB_LD + oo] = v.y;
        wbuf_t[(j + 2) * WB_LD + oo] = v.z;
        wbuf_t[(j + 3) * WB_LD + oo] = v.w;
    }
}

// LayerNorm over D=256 for 64 rows; warp-per-row, 8 rows per warp.
__device__ __forceinline__ void ln_rows(
    const float* __restrict__ src, int lds,
    float* dst, int ldd,
    const float* __restrict__ gg, const float* __restrict__ bb,
    bool leaky, int tid)
{
    int warp = tid >> 5, lane = tid & 31;
    for (int n = warp; n < 64; n += 8) {
        const float* row = src + (size_t)n * lds;
        float v[8];
        float s = 0.f, sq = 0.f;
#pragma unroll
        for (int i = 0; i < 8; i++) {
            float t = row[lane + 32 * i];
            v[i] = t;
            s += t;
            sq += t * t;
        }
#pragma unroll
        for (int off = 16; off > 0; off >>= 1) {
            s += __shfl_xor_sync(0xffffffffu, s, off);
            sq += __shfl_xor_sync(0xffffffffu, sq, off);
        }
        float mean = s * (1.0f / 256.0f);
        float var = sq * (1.0f / 256.0f) - mean * mean;
        float rstd = rsqrtf(var + 1e-5f);
#pragma unroll
        for (int i = 0; i < 8; i++) {
            int c = lane + 32 * i;
            float o = (v[i] - mean) * rstd * gg[c] + bb[c];
            if (leaky) o = (o >= 0.f) ? o : 0.1f * o;
            dst[(size_t)n * ldd + c] = o;
        }
    }
}

// Precompute softmax of the two static adjacency matrices (row softmax, 64x64).
__global__ void adj_softmax_kernel(const float* __restrict__ adj0,
                                   const float* __restrict__ adj1)
{
    const float* adj = blockIdx.x ? adj1 : adj0;
    float* dst = g_Ast + blockIdx.x * 4096;
    int r = threadIdx.x;  // 64 threads
    const float* row = adj + r * 64;
    float mx = -1e30f;
    for (int m = 0; m < 64; m++) mx = fmaxf(mx, row[m]);
    float s = 0.f;
    for (int m = 0; m < 64; m++) s += __expf(row[m] - mx);
    float inv = 1.0f / s;
    for (int m = 0; m < 64; m++) dst[r * 64 + m] = __expf(row[m] - mx) * inv;
}

__global__ void __launch_bounds__(256, 1) gconv_kernel(
    const float* __restrict__ graph,
    const float* __restrict__ ln_in_g, const float* __restrict__ ln_in_b,
    const float* __restrict__ th0, const float* __restrict__ ph0,
    const float* __restrict__ fcw0, const float* __restrict__ fcb0,
    const float* __restrict__ ln0_g, const float* __restrict__ ln0_b,
    const float* __restrict__ th1, const float* __restrict__ ph1,
    const float* __restrict__ fcw1, const float* __restrict__ fcb1,
    float* __restrict__ out)
{
    extern __shared__ float sm[];
    float* xs = sm + XS_OFF;
    float* qk = sm + QK_OFF;
    float* Ab = sm + AB_OFF;
    float* wb = sm + WB_OFF;

    int tid = threadIdx.x;
    int tx = tid & 15, ty = tid >> 4;
    int warp = tid >> 5, lane = tid & 31;
    int b = blockIdx.x;

    // ---- input LayerNorm: global graph[b] -> xs ----
    ln_rows(graph + (size_t)b * NN * ND, ND, xs, XS_LD, ln_in_g, ln_in_b, false, tid);
    __syncthreads();

#pragma unroll 1
    for (int l = 0; l < 2; l++) {
        const float* th = l ? th1 : th0;
        const float* ph = l ? ph1 : ph0;
        const float* fcw = l ? fcw1 : fcw0;
        const float* fcb = l ? fcb1 : fcb0;

        // ---- qk = xs @ [th;ph]^T  -> qk[64][256] (q: cols 0..127, k: 128..255) ----
        ull acc[4][8];
        zero_acc(acc);
        for (int k0 = 0; k0 < ND; k0 += 32) {
            __syncthreads();  // wb free
            stage_w(wb, th, ph, k0, tid);
            __syncthreads();
            gemm_tile(acc, xs, XS_LD, k0, wb, WB_LD, 32, tx, ty);
        }
        store_acc(acc, qk, QK_LD, nullptr, tx, ty);
        __syncthreads();

        // ---- scores[n][m] = dot(q[n], k[m]) / sqrt(128) -> Ab raw ----
        {
            float sacc[4][4] = {};
            for (int kk4 = 0; kk4 < NDH; kk4 += 4) {
                float4 aq[4], bk[4];
#pragma unroll
                for (int ri = 0; ri < 4; ri++)
                    aq[ri] = *(const float4*)(qk + (ty * 4 + ri) * QK_LD + kk4);
#pragma unroll
                for (int ci = 0; ci < 4; ci++)
                    bk[ci] = *(const float4*)(qk + (tx + 16 * ci) * QK_LD + 128 + kk4);
#pragma unroll
                for (int u = 0; u < 4; u++)
#pragma unroll
                    for (int ri = 0; ri < 4; ri++)
#pragma unroll
                        for (int ci = 0; ci < 4; ci++)
                            sacc[ri][ci] += f4c(aq[ri], u) * f4c(bk[ci], u);
            }
            const float sscale = 0.08838834764831845f;  // 1/sqrt(128)
#pragma unroll
            for (int ri = 0; ri < 4; ri++)
#pragma unroll
                for (int ci = 0; ci < 4; ci++)
                    Ab[(ty * 4 + ri) * A_LD + tx + 16 * ci] = sacc[ri][ci] * sscale;
        }
        __syncthreads();

        // ---- A_hat = A_static + row_softmax(scores), in place in Ab ----
        {
            const float* Ast = g_Ast + l * 4096;
            for (int n = warp; n < 64; n += 8) {
                float v0 = Ab[n * A_LD + lane];
                float v1 = Ab[n * A_LD + 32 + lane];
                float mx = fmaxf(v0, v1);
#pragma unroll
                for (int off = 16; off > 0; off >>= 1)
                    mx = fmaxf(mx, __shfl_xor_sync(0xffffffffu, mx, off));
                float e0 = __expf(v0 - mx);
                float e1 = __expf(v1 - mx);
                float ss = e0 + e1;
#pragma unroll
                for (int off = 16; off > 0; off >>= 1)
                    ss += __shfl_xor_sync(0xffffffffu, ss, off);
                float inv = 1.0f / ss;
                Ab[n * A_LD + lane] = Ast[n * 64 + lane] + e0 * inv;
                Ab[n * A_LD + 32 + lane] = Ast[n * 64 + 32 + lane] + e1 * inv;
            }
        }
        __syncthreads();

        // ---- agg = A_hat @ xs -> qk buffer (reused) ----
        zero_acc(acc);
        gemm_tile(acc, Ab, A_LD, 0, xs, XS_LD, 64, tx, ty);
        store_acc(acc, qk, QK_LD, nullptr, tx, ty);
        __syncthreads();

        // ---- fc: out = agg @ fcw^T + fcb ----
        zero_acc(acc);
        for (int k0 = 0; k0 < ND; k0 += 32) {
            __syncthreads();
            stage_w(wb, fcw, fcw + 128 * ND, k0, tid);
            __syncthreads();
            gemm_tile(acc, qk, QK_LD, k0, wb, WB_LD, 32, tx, ty);
        }
        if (l == 0) {
            store_acc(acc, xs, XS_LD, fcb, tx, ty);
            __syncthreads();
            // LN + LeakyReLU(0.1), in place in xs
            ln_rows(xs, XS_LD, xs, XS_LD, ln0_g, ln0_b, true, tid);
            __syncthreads();
        } else {
            store_acc(acc, out + (size_t)b * NN * ND, ND, fcb, tx, ty);
        }
    }
}

extern "C" void kernel_launch(void* const* d_in, const int* in_sizes, int n_in,
                              void* d_out, int out_size)
{
    const float* graph   = (const float*)d_in[0];
    const float* ln_in_g = (const float*)d_in[1];
    const float* ln_in_b = (const float*)d_in[2];
    const float* adj0    = (const float*)d_in[3];
    const float* th0     = (const float*)d_in[4];
    const float* ph0     = (const float*)d_in[5];
    const float* fcw0    = (const float*)d_in[6];
    const float* fcb0    = (const float*)d_in[7];
    const float* ln0_g   = (const float*)d_in[8];
    const float* ln0_b   = (const float*)d_in[9];
    const float* adj1    = (const float*)d_in[10];
    const float* th1     = (const float*)d_in[11];
    const float* ph1     = (const float*)d_in[12];
    const float* fcw1    = (const float*)d_in[13];
    const float* fcb1    = (const float*)d_in[14];
    float* out = (float*)d_out;

    cudaFuncSetAttribute(gconv_kernel,
                         cudaFuncAttributeMaxDynamicSharedMemorySize, SMEM_BYTES);

    adj_softmax_kernel<<<2, 64>>>(adj0, adj1);
    gconv_kernel<<<NB, 256, SMEM_BYTES>>>(
        graph, ln_in_g, ln_in_b,
        th0, ph0, fcw0, fcb0, ln0_g, ln0_b,
        th1, ph1, fcw1, fcb1, out);
}